// round 4
// baseline (speedup 1.0000x reference)
#include <cuda_runtime.h>

#define H      20
#define NEX    13
#define EMBD   3
#define FIN    3
#define FOUT   5
#define HIN    8
#define HID    10
#define BLK    128
#define FROW   (H*FIN)    // 60 floats of f per row
#define WSTR   48         // per-head packed weight stride (floats)
#define ESTR   10         // E' row stride (floats), 8B-aligned rows
#define FSTR   31         // s_f row stride (odd -> conflict-free per-lane reads)

typedef unsigned long long u64;

// g_E[(h*NEX+idx)*10 + j] = emb[idx]@W1[h][0:3,j] + b1[h][j] + bf@W1[h][3:8,j]
// g_W[h*48 + c*12 + j]    = (Wf @ W1[h][3:8])[c][j]  (c=0..2, j=0..9; pads 0)
// g_W[h*48 + 36 + j]      = W2[h][j];  [46]=b2[h];  [47]=Wo[h]
__device__   __align__(16) float g_E[H * NEX * ESTR];   // 2600 floats
__device__   __align__(16) float g_W[H * WSTR];         // 960 floats
__constant__ __align__(16) float c_W[H * WSTR];         // copy of g_W (uniform access)

__global__ void prep_kernel(const float* __restrict__ emb,
                            const float* __restrict__ Wf,
                            const float* __restrict__ bf,
                            const float* __restrict__ W1,
                            const float* __restrict__ b1,
                            const float* __restrict__ W2,
                            const float* __restrict__ b2,
                            const float* __restrict__ Wo)
{
    const int g = blockIdx.x * blockDim.x + threadIdx.x;
    const int NE = H * NEX * ESTR;          // 2600
    if (g < NE) {
        const int h   = g / (NEX * ESTR);
        const int r   = g % (NEX * ESTR);
        const int idx = r / ESTR;
        const int j   = r % ESTR;
        float v = b1[h * HID + j];
#pragma unroll
        for (int k = 0; k < FOUT; k++)
            v = fmaf(bf[k], W1[(h * HIN + 3 + k) * HID + j], v);
#pragma unroll
        for (int d = 0; d < EMBD; d++)
            v = fmaf(emb[idx * EMBD + d], W1[(h * HIN + d) * HID + j], v);
        g_E[g] = v;
    } else if (g < NE + H * WSTR) {
        const int w = g - NE;
        const int h = w / WSTR;
        const int j = w % WSTR;
        float v = 0.0f;
        if (j < 36) {
            const int c  = j / 12;
            const int jj = j % 12;
            if (jj < HID) {
#pragma unroll
                for (int k = 0; k < FOUT; k++)
                    v = fmaf(Wf[c * FOUT + k], W1[(h * HIN + 3 + k) * HID + jj], v);
            }
        } else if (j < 46) {
            v = W2[h * HID + (j - 36)];
        } else if (j == 46) {
            v = b2[h];
        } else {
            v = Wo[h];
        }
        g_W[w] = v;
    }
}

// ---- packed fp32x2 helpers ----
__device__ __forceinline__ u64 pk2(float x, float y) {
    u64 r; asm("mov.b64 %0, {%1, %2};" : "=l"(r) : "f"(x), "f"(y)); return r;
}
__device__ __forceinline__ void up2(u64 v, float& x, float& y) {
    asm("mov.b64 {%0, %1}, %2;" : "=f"(x), "=f"(y) : "l"(v));
}
__device__ __forceinline__ u64 ffma2(u64 a, u64 b, u64 c) {
    u64 d; asm("fma.rn.f32x2 %0, %1, %2, %3;" : "=l"(d) : "l"(a), "l"(b), "l"(c)); return d;
}

__device__ __forceinline__ void heads10(int hbase, const float* __restrict__ my_f,
                                        const unsigned char* __restrict__ my_e,
                                        const float* __restrict__ sE, float& acc)
{
#pragma unroll 2
    for (int hh = 0; hh < 10; hh++) {
        const int h = hbase + hh;
        const int idx = (int)my_e[h];

        const float* Ep = &sE[(h * NEX + idx) * ESTR];
        u64 t0 = *reinterpret_cast<const u64*>(Ep + 0);
        u64 t1 = *reinterpret_cast<const u64*>(Ep + 2);
        u64 t2 = *reinterpret_cast<const u64*>(Ep + 4);
        u64 t3 = *reinterpret_cast<const u64*>(Ep + 6);
        u64 t4 = *reinterpret_cast<const u64*>(Ep + 8);

        const float fv[3] = { my_f[hh * 3 + 0], my_f[hh * 3 + 1], my_f[hh * 3 + 2] };

#pragma unroll
        for (int c = 0; c < 3; c++) {
            const float4 wa = *reinterpret_cast<const float4*>(&c_W[h * WSTR + c * 12 + 0]);
            const float4 wb = *reinterpret_cast<const float4*>(&c_W[h * WSTR + c * 12 + 4]);
            const float2 wc = *reinterpret_cast<const float2*>(&c_W[h * WSTR + c * 12 + 8]);
            const u64 fc2 = pk2(fv[c], fv[c]);
            t0 = ffma2(fc2, pk2(wa.x, wa.y), t0);
            t1 = ffma2(fc2, pk2(wa.z, wa.w), t1);
            t2 = ffma2(fc2, pk2(wb.x, wb.y), t2);
            t3 = ffma2(fc2, pk2(wb.z, wb.w), t3);
            t4 = ffma2(fc2, pk2(wc.x, wc.y), t4);
        }

        const float4 v0 = *reinterpret_cast<const float4*>(&c_W[h * WSTR + 36]);
        const float4 v1 = *reinterpret_cast<const float4*>(&c_W[h * WSTR + 40]);
        const float4 v2 = *reinterpret_cast<const float4*>(&c_W[h * WSTR + 44]); // W2[8],W2[9],b2,Wo

        float a0, a1;
        #define LK(v) fmaxf((v), 0.01f * (v))
        float z = v2.z;                                   // b2
        up2(t0, a0, a1); z = fmaf(LK(a0), v0.x, z); z = fmaf(LK(a1), v0.y, z);
        up2(t1, a0, a1); z = fmaf(LK(a0), v0.z, z); z = fmaf(LK(a1), v0.w, z);
        up2(t2, a0, a1); z = fmaf(LK(a0), v1.x, z); z = fmaf(LK(a1), v1.y, z);
        up2(t3, a0, a1); z = fmaf(LK(a0), v1.z, z); z = fmaf(LK(a1), v1.w, z);
        up2(t4, a0, a1); z = fmaf(LK(a0), v2.x, z); z = fmaf(LK(a1), v2.y, z);
        #undef LK

        const float sp = fmaxf(z, 0.0f) + __logf(1.0f + __expf(-fabsf(z)));
        acc = fmaf(sp, v2.w, acc);                        // Wo
    }
}

__global__ __launch_bounds__(BLK, 7)
void airfit_main(const int*   __restrict__ e,
                 const float* __restrict__ f,
                 const float* __restrict__ bo,
                 float*       __restrict__ out,
                 int n)
{
    // 28832 bytes static shared
    __shared__ __align__(16) float        s_E[H * NEX * ESTR];  // 10400 B
    __shared__              float         s_f[BLK * FSTR];      // 15872 B
    __shared__              unsigned int  s_e[BLK * H / 4];     //  2560 B

    const int tid = threadIdx.x;
    const long long b0 = (long long)blockIdx.x * BLK;
    const long long b  = b0 + tid;
    const bool active = (b < n);

    int rows = n - (int)b0;
    if (rows > BLK) rows = BLK;
    if (rows < 0)   rows = 0;

    // ---- stage E' (uniform float4 copies) ----
    {
        const float4* src = reinterpret_cast<const float4*>(g_E);
        float4*       dst = reinterpret_cast<float4*>(s_E);
        for (int i = tid; i < H * NEX * ESTR / 4; i += BLK) dst[i] = src[i];
    }

    // ---- stage e coalesced: int4 loads, 4 indices packed per word ----
    {
        const int4* eg = reinterpret_cast<const int4*>(e + b0 * H);
        const int nv = rows * (H / 4);                    // rows*5
        for (int v = tid; v < nv; v += BLK) {
            int4 val = eg[v];
            s_e[v] = (unsigned)(val.x & 0xFF)
                   | ((unsigned)(val.y & 0xFF) << 8)
                   | ((unsigned)(val.z & 0xFF) << 16)
                   | ((unsigned)(val.w & 0xFF) << 24);
        }
    }

    const unsigned char* my_e = reinterpret_cast<const unsigned char*>(s_e) + tid * H;
    const float* my_f = &s_f[tid * FSTR];
    float acc = __ldg(bo);

#pragma unroll 1
    for (int p = 0; p < 2; p++) {
        if (p) __syncthreads();   // protect s_f still in use by phase 0 consumers

        // ---- stage 30-column half of f: coalesced float2 loads ----
        {
            const float2* fg = reinterpret_cast<const float2*>(f) + b0 * (FROW / 2);
            const int nf2 = rows * 15;
            for (int v = tid; v < nf2; v += BLK) {
                const int row = v / 15;
                const int j   = v % 15;
                const float2 val = fg[row * 30 + p * 15 + j];
                s_f[row * FSTR + 2 * j + 0] = val.x;
                s_f[row * FSTR + 2 * j + 1] = val.y;
            }
        }
        __syncthreads();

        if (active) heads10(p * 10, my_f, my_e, s_E, acc);
    }

    if (active) out[b] = acc;
}

extern "C" void kernel_launch(void* const* d_in, const int* in_sizes, int n_in,
                              void* d_out, int out_size)
{
    const int*   e   = (const int*)  d_in[0];
    const float* f   = (const float*)d_in[1];
    const float* emb = (const float*)d_in[2];
    const float* Wf  = (const float*)d_in[3];
    const float* bf  = (const float*)d_in[4];
    const float* W1  = (const float*)d_in[5];
    const float* b1  = (const float*)d_in[6];
    const float* W2  = (const float*)d_in[7];
    const float* b2  = (const float*)d_in[8];
    const float* Wo  = (const float*)d_in[9];
    const float* bo  = (const float*)d_in[10];
    float* out = (float*)d_out;

    const int n = in_sizes[0] / H;

    prep_kernel<<<(H * NEX * ESTR + H * WSTR + 255) / 256, 256>>>(emb, Wf, bf, W1, b1, W2, b2, Wo);

    // publish packed weights to constant memory (D2D async copy, graph-capturable)
    void* gW_dev = nullptr;
    cudaGetSymbolAddress(&gW_dev, g_W);
    cudaMemcpyToSymbolAsync(c_W, gW_dev, sizeof(float) * H * WSTR, 0,
                            cudaMemcpyDeviceToDevice, 0);

    const int grid = (n + BLK - 1) / BLK;
    airfit_main<<<grid, BLK>>>(e, f, bo, out, n);
}

// round 5
// speedup vs baseline: 1.0795x; 1.0795x over previous
#include <cuda_runtime.h>

#define H      20
#define NEX    13
#define EMBD   3
#define FIN    3
#define FOUT   5
#define HIN    8
#define HID    10
#define BLK    128
#define FROW   (H*FIN)    // 60 floats of f per row
#define WSTR   48         // per-head packed weight stride (floats)
#define ESTR   12         // E' row stride (floats) -> 48B, 16B-aligned rows
#define FSTR   62         // s_f row stride: 8B-aligned rows, 2-way LDS conflicts only

typedef unsigned long long u64;

// g_E[(h*NEX+idx)*12 + j] = emb[idx]@W1[h][0:3,j] + b1[h][j] + bf@W1[h][3:8,j]  (j=0..9, pad 0)
// g_W[h*48 + c*12 + j]    = (Wf @ W1[h][3:8])[c][j]  (c=0..2, j=0..9; pads 0)
// g_W[h*48 + 36 + j]      = W2[h][j];  [46]=b2[h];  [47]=Wo[h]
__device__   __align__(16) float g_E[H * NEX * ESTR];   // 3120 floats
__device__   __align__(16) float g_W[H * WSTR];         // 960 floats
__constant__ __align__(16) float c_W[H * WSTR];

__global__ void prep_kernel(const float* __restrict__ emb,
                            const float* __restrict__ Wf,
                            const float* __restrict__ bf,
                            const float* __restrict__ W1,
                            const float* __restrict__ b1,
                            const float* __restrict__ W2,
                            const float* __restrict__ b2,
                            const float* __restrict__ Wo)
{
    const int g = blockIdx.x * blockDim.x + threadIdx.x;
    const int NE = H * NEX * ESTR;          // 3120
    if (g < NE) {
        const int h   = g / (NEX * ESTR);
        const int r   = g % (NEX * ESTR);
        const int idx = r / ESTR;
        const int j   = r % ESTR;
        float v = 0.0f;
        if (j < HID) {
            v = b1[h * HID + j];
#pragma unroll
            for (int k = 0; k < FOUT; k++)
                v = fmaf(bf[k], W1[(h * HIN + 3 + k) * HID + j], v);
#pragma unroll
            for (int d = 0; d < EMBD; d++)
                v = fmaf(emb[idx * EMBD + d], W1[(h * HIN + d) * HID + j], v);
        }
        g_E[g] = v;
    } else if (g < NE + H * WSTR) {
        const int w = g - NE;
        const int h = w / WSTR;
        const int j = w % WSTR;
        float v = 0.0f;
        if (j < 36) {
            const int c  = j / 12;
            const int jj = j % 12;
            if (jj < HID) {
#pragma unroll
                for (int k = 0; k < FOUT; k++)
                    v = fmaf(Wf[c * FOUT + k], W1[(h * HIN + 3 + k) * HID + jj], v);
            }
        } else if (j < 46) {
            v = W2[h * HID + (j - 36)];
        } else if (j == 46) {
            v = b2[h];
        } else {
            v = Wo[h];
        }
        g_W[w] = v;
    }
}

// packed fp32x2 on aligned register pairs (no pack/unpack MOVs needed)
__device__ __forceinline__ double ffma2(double a, double b, double c) {
    double d; asm("fma.rn.f32x2 %0, %1, %2, %3;" : "=d"(d) : "d"(a), "d"(b), "d"(c)); return d;
}
union D2 { double d; float2 f; };

__global__ __launch_bounds__(BLK, 4)
void airfit_main(const int*   __restrict__ e,
                 const float* __restrict__ f,
                 const float* __restrict__ bo,
                 float*       __restrict__ out,
                 int n)
{
    // 46784 bytes static shared -> 4 CTAs/SM
    __shared__ __align__(16) float        s_E[H * NEX * ESTR];  // 12480 B
    __shared__ __align__(16) float        s_f[BLK * FSTR];      // 31744 B
    __shared__              unsigned int  s_e[BLK * H / 4];     //  2560 B

    const int tid = threadIdx.x;
    const long long b0 = (long long)blockIdx.x * BLK;
    const long long b  = b0 + tid;
    const bool active = (b < n);

    int rows = n - (int)b0;
    if (rows > BLK) rows = BLK;
    if (rows < 0)   rows = 0;

    // ---- stage E' (uniform float4 copies, 780 f4) ----
    {
        const float4* src = reinterpret_cast<const float4*>(g_E);
        float4*       dst = reinterpret_cast<float4*>(s_E);
        for (int i = tid; i < H * NEX * ESTR / 4; i += BLK) dst[i] = src[i];
    }

    // ---- stage e coalesced: int4 loads, 4 indices packed per word ----
    {
        const int4* eg = reinterpret_cast<const int4*>(e + b0 * H);
        const int nv = rows * (H / 4);                    // rows*5 words
        for (int v = tid; v < nv; v += BLK) {
            int4 val = eg[v];
            s_e[v] = (unsigned)(val.x & 0xFF)
                   | ((unsigned)(val.y & 0xFF) << 8)
                   | ((unsigned)(val.z & 0xFF) << 16)
                   | ((unsigned)(val.w & 0xFF) << 24);
        }
    }

    // ---- stage f coalesced float4 -> stride-62 rows via STS.64 pairs ----
    {
        const float4* fg = reinterpret_cast<const float4*>(f + b0 * FROW);
        const int nf4 = rows * (FROW / 4);                // rows*15
        for (int v = tid; v < nf4; v += BLK) {
            float4 val = fg[v];
            const int row = v / 15;
            const int col = 4 * (v % 15);
            float2* dst = reinterpret_cast<float2*>(&s_f[row * FSTR + col]);
            dst[0] = make_float2(val.x, val.y);
            dst[1] = make_float2(val.z, val.w);
        }
    }
    __syncthreads();

    float accA = active ? __ldg(bo) : 0.0f;
    float accB = 0.0f;

    if (active) {
        // prefetch this row's 20 indices into 5 registers
        unsigned ew[5];
#pragma unroll
        for (int c = 0; c < 5; c++) ew[c] = s_e[tid * 5 + c];

        const float* my_f = &s_f[tid * FSTR];

#pragma unroll
        for (int h = 0; h < H; h++) {
            const int idx = (int)((ew[h >> 2] >> ((h & 3) * 8)) & 0xFF);

            // accumulators from bias-folded embedding table (LDS.128 x2 + LDS.64)
            const float* Ep = &s_E[(h * NEX + idx) * ESTR];
            const double2 ea = *reinterpret_cast<const double2*>(Ep);
            const double2 eb = *reinterpret_cast<const double2*>(Ep + 4);
            double t0 = ea.x, t1 = ea.y, t2 = eb.x, t3 = eb.y;
            double t4 = *reinterpret_cast<const double*>(Ep + 8);

            const float* Wh = &c_W[h * WSTR];
#pragma unroll
            for (int c = 0; c < 3; c++) {
                const float fc = my_f[h * 3 + c];
                D2 fcd; fcd.f = make_float2(fc, fc);
                const double2 wa = *reinterpret_cast<const double2*>(Wh + c * 12);
                const double2 wb = *reinterpret_cast<const double2*>(Wh + c * 12 + 4);
                const double  wc = *reinterpret_cast<const double*>(Wh + c * 12 + 8);
                t0 = ffma2(fcd.d, wa.x, t0);
                t1 = ffma2(fcd.d, wa.y, t1);
                t2 = ffma2(fcd.d, wb.x, t2);
                t3 = ffma2(fcd.d, wb.y, t3);
                t4 = ffma2(fcd.d, wc,   t4);
            }

            // leaky_relu + W2 dot as two parallel trees
            const float4 v0 = *reinterpret_cast<const float4*>(Wh + 36);
            const float4 v1 = *reinterpret_cast<const float4*>(Wh + 40);
            const float4 v2 = *reinterpret_cast<const float4*>(Wh + 44); // W2[8],W2[9],b2,Wo
            D2 u0, u1, u2, u3, u4;
            u0.d = t0; u1.d = t1; u2.d = t2; u3.d = t3; u4.d = t4;
            #define LK(v) fmaxf((v), 0.01f * (v))
            float za = LK(u0.f.x) * v0.x;
            float zb = fmaf(LK(u0.f.y), v0.y, v2.z);      // + b2
            za = fmaf(LK(u1.f.x), v0.z, za);
            zb = fmaf(LK(u1.f.y), v0.w, zb);
            za = fmaf(LK(u2.f.x), v1.x, za);
            zb = fmaf(LK(u2.f.y), v1.y, zb);
            za = fmaf(LK(u3.f.x), v1.z, za);
            zb = fmaf(LK(u3.f.y), v1.w, zb);
            za = fmaf(LK(u4.f.x), v2.x, za);
            zb = fmaf(LK(u4.f.y), v2.y, zb);
            #undef LK
            const float z = za + zb;

            const float sp = fmaxf(z, 0.0f) + __logf(1.0f + __expf(-fabsf(z)));
            if (h & 1) accB = fmaf(sp, v2.w, accB);
            else       accA = fmaf(sp, v2.w, accA);
        }

        out[b] = accA + accB;
    }
}

extern "C" void kernel_launch(void* const* d_in, const int* in_sizes, int n_in,
                              void* d_out, int out_size)
{
    const int*   e   = (const int*)  d_in[0];
    const float* f   = (const float*)d_in[1];
    const float* emb = (const float*)d_in[2];
    const float* Wf  = (const float*)d_in[3];
    const float* bf  = (const float*)d_in[4];
    const float* W1  = (const float*)d_in[5];
    const float* b1  = (const float*)d_in[6];
    const float* W2  = (const float*)d_in[7];
    const float* b2  = (const float*)d_in[8];
    const float* Wo  = (const float*)d_in[9];
    const float* bo  = (const float*)d_in[10];
    float* out = (float*)d_out;

    const int n = in_sizes[0] / H;

    const int prep_elems = H * NEX * ESTR + H * WSTR;   // 4080
    prep_kernel<<<(prep_elems + 255) / 256, 256>>>(emb, Wf, bf, W1, b1, W2, b2, Wo);

    void* gW_dev = nullptr;
    cudaGetSymbolAddress(&gW_dev, g_W);
    cudaMemcpyToSymbolAsync(c_W, gW_dev, sizeof(float) * H * WSTR, 0,
                            cudaMemcpyDeviceToDevice, 0);

    const int grid = (n + BLK - 1) / BLK;
    airfit_main<<<grid, BLK>>>(e, f, bo, out, n);
}